// round 15
// baseline (speedup 1.0000x reference)
#include <cuda_runtime.h>
#include <cuda_fp16.h>
#include <cstdint>

#define N_TOKENS 4096
#define D_MODEL  4096
#define HIDDEN   16384

// ---------------- device scratch (no runtime allocation allowed) ----------------
__device__ __align__(1024) __half g_x16[(size_t)N_TOKENS * D_MODEL];   //  32 MB
__device__ __align__(1024) __half g_w1 [(size_t)HIDDEN   * D_MODEL];   // 128 MB
__device__ __align__(1024) __half g_w2 [(size_t)D_MODEL  * HIDDEN];    // 128 MB
__device__ __align__(1024) __half g_h  [(size_t)N_TOKENS * HIDDEN];    // 128 MB

// ---------------- helpers ----------------
static __device__ __forceinline__ uint32_t smem_u32(const void* p) {
    uint32_t a;
    asm("{ .reg .u64 t; cvta.to.shared.u64 t, %1; cvt.u32.u64 %0, t; }" : "=r"(a) : "l"(p));
    return a;
}

static __device__ __forceinline__ void cp_async16(uint32_t dst, const void* src) {
    asm volatile("cp.async.cg.shared.global [%0], [%1], 16;" :: "r"(dst), "l"(src) : "memory");
}

#define MBARRIER_INIT(addr, cnt) \
    asm volatile("mbarrier.init.shared.b64 [%0], %1;" :: "r"(addr), "r"(cnt) : "memory")

// arrive on mbarrier when all of this thread's prior cp.asyncs have completed
#define CPASYNC_ARRIVE(addr) \
    asm volatile("cp.async.mbarrier.arrive.noinc.shared.b64 [%0];" :: "r"(addr) : "memory")

// acquire wait: post-wait generic-proxy reads (LDSM) need the acquire
#define MBAR_WAIT(addr, ph) do {                                                     \
    uint32_t _m = (addr); uint32_t _p = (uint32_t)(ph); uint32_t _done;              \
    asm volatile("{\n\t.reg .pred p;\n\t"                                            \
        "mbarrier.try_wait.parity.acquire.cta.shared::cta.b64 p, [%1], %2;\n\t"      \
        "selp.b32 %0, 1, 0, p;\n\t}"                                                 \
        : "=r"(_done) : "r"(_m), "r"(_p) : "memory");                                \
    if (!_done) {                                                                    \
        asm volatile("{\n\t.reg .pred P1;\n\t"                                       \
            "WL_%=:\n\t"                                                             \
            "mbarrier.try_wait.parity.acquire.cta.shared::cta.b64 P1, [%0], %1, 0x989680;\n\t" \
            "@P1 bra.uni WD_%=;\n\t"                                                 \
            "bra.uni WL_%=;\n\t"                                                     \
            "WD_%=:\n\t}"                                                            \
            :: "r"(_m), "r"(_p) : "memory");                                         \
    }                                                                                \
} while (0)

// named barriers for stage-empty tracking (ids 1..3; 0 reserved for __syncthreads)
#define NBAR_ARRIVE(id) \
    asm volatile("bar.arrive %0, 512;" :: "r"(id) : "memory")
#define NBAR_SYNC(id) \
    asm volatile("bar.sync %0, 512;" :: "r"(id) : "memory")

static __device__ __forceinline__ void ldmatrix_x4(uint32_t& r0, uint32_t& r1,
                                                   uint32_t& r2, uint32_t& r3, uint32_t addr) {
    asm volatile("ldmatrix.sync.aligned.m8n8.x4.shared.b16 {%0,%1,%2,%3}, [%4];"
                 : "=r"(r0), "=r"(r1), "=r"(r2), "=r"(r3) : "r"(addr));
}

static __device__ __forceinline__ void mma_16816(float* c, const uint32_t* a,
                                                 const uint32_t* b) {
    asm volatile(
        "mma.sync.aligned.m16n8k16.row.col.f32.f16.f16.f32 "
        "{%0,%1,%2,%3}, {%4,%5,%6,%7}, {%8,%9}, {%0,%1,%2,%3};"
        : "+f"(c[0]), "+f"(c[1]), "+f"(c[2]), "+f"(c[3])
        : "r"(a[0]), "r"(a[1]), "r"(a[2]), "r"(a[3]), "r"(b[0]), "r"(b[1]));
}

static __device__ __forceinline__ float gelu_tanh(float v) {
    // JAX default: gelu(x) = 0.5 x (1 + tanh(sqrt(2/pi) (x + 0.044715 x^3)))
    float u = 0.7978845608028654f * (v + 0.044715f * v * v * v);
    float e = __expf(2.0f * u);
    float t = 1.0f - 2.0f / (e + 1.0f);     // tanh(u), correct limits at +-inf
    return 0.5f * v * (1.0f + t);
}

// ---------------- fused prep kernel: x->fp16 + both int4 dequants, 32B/thread ----
static __device__ __forceinline__ uint32_t unpack_pair(int p) {
    p &= 255;
    __half2 h = __halves2half2(__int2half_rn((p >> 4) - 8), __int2half_rn((p & 15) - 8));
    return reinterpret_cast<uint32_t&>(h);
}

__global__ void k_prep(const float4* __restrict__ x, uint2* __restrict__ x16,
                       const int4* __restrict__ p1, uint4* __restrict__ w1,
                       const int4* __restrict__ p2, uint4* __restrict__ w2,
                       int n4x, int n41, int n42) {
    int i = (blockIdx.x * blockDim.x + threadIdx.x) * 2;   // 2 x 16B chunks per thread
    if (i < n4x) {
#pragma unroll
        for (int j = 0; j < 2; j++) {
            float4 v = x[i + j];
            __half2 a = __floats2half2_rn(v.x, v.y);
            __half2 b = __floats2half2_rn(v.z, v.w);
            uint2 o;
            o.x = reinterpret_cast<uint32_t&>(a);
            o.y = reinterpret_cast<uint32_t&>(b);
            x16[i + j] = o;
        }
        return;
    }
    i -= n4x;
    if (i < n41) {
#pragma unroll
        for (int j = 0; j < 2; j++) {
            int4 v = p1[i + j];
            uint4 o;
            o.x = unpack_pair(v.x); o.y = unpack_pair(v.y);
            o.z = unpack_pair(v.z); o.w = unpack_pair(v.w);
            w1[i + j] = o;
        }
        return;
    }
    i -= n41;
    if (i < n42) {
#pragma unroll
        for (int j = 0; j < 2; j++) {
            int4 v = p2[i + j];
            uint4 o;
            o.x = unpack_pair(v.x); o.y = unpack_pair(v.y);
            o.z = unpack_pair(v.z); o.w = unpack_pair(v.w);
            w2[i + j] = o;
        }
    }
}

// ---------------- HMMA GEMM: C[M,N] = A[M,0:KSPAN] * B[N,0:KSPAN]^T ----------------
// A, B fp16 K-major with COMPILE-TIME row stride KLD and span KSPAN.
// CTA 128x128x64, 256 thr, 8 warps (2x4), warp tile 64x32, 3-stage pipeline:
// full = mbarrier armed by cp.async completion; empty = named barrier (ids 1..3,
// bar.arrive at last stage read + bar.sync at produce point, count 512).
// Fully double-buffered A+B fragments; waits issued after MMA batches so the
// tensor-pipe backlog covers them.
template <bool GELU_OUT, typename OutT, int KLD, int KSPAN>
__global__ void __launch_bounds__(256, 2)
qmlp_gemm(const __half* __restrict__ A, const __half* __restrict__ B,
          const float* __restrict__ scales, OutT* __restrict__ C,
          int M, int Ncols)
{
    constexpr int S        = 3;
    constexpr int A_BYTES  = 128 * 128;         // 128 rows x 64 halves
    constexpr int B_BYTES  = 128 * 128;
    constexpr int STAGE    = A_BYTES + B_BYTES; // 32 KB
    constexpr int NIT      = KSPAN >> 6;        // K-tiles of 64

    extern __shared__ unsigned char dynsmem[];
    __shared__ __align__(8) uint64_t s_mbar[S];       // full[0..2]

    const uint32_t sbase0 = smem_u32(dynsmem);
    const uint32_t tiles  = (sbase0 + 1023u) & ~1023u;   // 1KB-align (XOR trick needs 128B)
    const uint32_t mfull  = smem_u32(&s_mbar[0]);        // + b*8

    const int tid = threadIdx.x;
    const int wid = tid >> 5;
    const int lid = tid & 31;
    const int wm  = wid & 1;                    // 2 warps along M
    const int wn  = wid >> 1;                   // 4 warps along N

    // block -> (m-tile, n-tile), grouped along M for L2 reuse of B
    const int mt_tiles = M >> 7;
    const int nt_tiles = Ncols >> 7;
    const int GROUPM = 8;
    const int per_group = GROUPM * nt_tiles;
    int g  = blockIdx.x / per_group;
    int rr = blockIdx.x - g * per_group;
    int gm = mt_tiles - g * GROUPM; if (gm > GROUPM) gm = GROUPM;
    const int m0 = (g * GROUPM + (rr % gm)) << 7;
    const int n0 = (rr / gm) << 7;

    if (tid == 0) {
#pragma unroll
        for (int b = 0; b < S; b++)
            MBARRIER_INIT(mfull + b * 8, 256);  // flips when all threads' cp.asyncs land
    }
    __syncthreads();                            // barriers visible; only CTA-wide sync

    // ---- precomputed per-thread offsets (SW128 decomposition) ----
    const int lrow = tid >> 3;                  // 0..31
    const int lseg = tid & 7;                   // 16B segment in 128B row
    const uint32_t dst0 = (uint32_t)(lrow * 128 + ((lseg * 16) ^ ((lrow & 7) << 4)));

    const int a_row = wm * 64 + (lid & 15);
    const uint32_t a_cb = (uint32_t)((lid >> 4) << 4);            // 0 or 16 bytes
    const int b_row = wn * 32 + (lid & 7) + ((lid & 16) ? 8 : 0);
    const uint32_t b_cb = (uint32_t)((lid & 8) ? 16 : 0);
    const uint32_t aP0 = (uint32_t)(a_row * 128) + (a_cb ^ (uint32_t)((a_row & 7) << 4));
    const uint32_t bP0 = (uint32_t)(b_row * 128) + (b_cb ^ (uint32_t)((b_row & 7) << 4));

    // global source pointers, advanced 64 halves (128B) per stage
    const __half* gA = A + (size_t)(m0 + lrow) * KLD + lseg * 8;
    const __half* gB = B + (size_t)(n0 + lrow) * KLD + lseg * 8;
    constexpr size_t rowblk = (size_t)32 * KLD;   // 32-row chunk stride (elements)

    auto load_stage_to = [&](uint32_t st, const __half* a_, const __half* b_) {
#pragma unroll
        for (int i = 0; i < 4; i++)
            cp_async16(st + dst0 + i * 4096, a_ + i * rowblk);
#pragma unroll
        for (int i = 0; i < 4; i++)
            cp_async16(st + A_BYTES + dst0 + i * 4096, b_ + i * rowblk);
    };

    float c[4][4][4];
#pragma unroll
    for (int i = 0; i < 4; i++)
#pragma unroll
        for (int j = 0; j < 4; j++)
#pragma unroll
            for (int k = 0; k < 4; k++) c[i][j][k] = 0.0f;

    // fully double-buffered fragments
    uint32_t afr[2][4][4];
    uint32_t bfr[2][4][2];

    auto ldA = [&](int buf, uint32_t baseA, uint32_t kx) {
        const uint32_t bk = baseA ^ kx;
#pragma unroll
        for (int mi = 0; mi < 4; mi++)
            ldmatrix_x4(afr[buf][mi][0], afr[buf][mi][1], afr[buf][mi][2], afr[buf][mi][3],
                        bk + mi * 2048);
    };
    auto ldB = [&](int buf, uint32_t baseB, uint32_t kx) {
        const uint32_t bk = baseB ^ kx;
#pragma unroll
        for (int p = 0; p < 2; p++) {
            uint32_t r0, r1, r2, r3;
            ldmatrix_x4(r0, r1, r2, r3, bk + p * 2048);
            bfr[buf][2 * p][0] = r0; bfr[buf][2 * p][1] = r1;
            bfr[buf][2 * p + 1][0] = r2; bfr[buf][2 * p + 1][1] = r3;
        }
    };
    auto mma_batch = [&](int fb) {
#pragma unroll
        for (int mi = 0; mi < 4; mi++)
#pragma unroll
            for (int ni = 0; ni < 4; ni++)
                mma_16816(c[mi][ni], afr[fb][mi], bfr[fb][ni]);
    };

    // prologue: stages 0 and 1, each armed with a DMA-completion arrive
    load_stage_to(tiles, gA, gB);
    CPASYNC_ARRIVE(mfull + 0 * 8);
    load_stage_to(tiles + STAGE, gA + 64, gB + 64);
    CPASYNC_ARRIVE(mfull + 1 * 8);
    gA += 128; gB += 128;

    // consumer cursor: buffer cidx, parity cph
    int cidx = 0, cph = 0;
    uint32_t cbuf = tiles;
    // producer cursor: buffer pidx = (it+2)%3
    int pidx = 2;
    uint32_t pbuf = tiles + 2 * STAGE;

    // consumer prologue: wait stage 0, load ks=0 frags into buffer 0
    MBAR_WAIT(mfull + 0, 0);
    uint32_t baseA = cbuf + aP0;
    uint32_t baseB = cbuf + A_BYTES + bP0;
    ldA(0, baseA, 0);
    ldB(0, baseB, 0);

#pragma unroll 1
    for (int it = 0; it < NIT; it++) {
        // ks=0 MMAs first — their drain covers the empty-sync below
        mma_batch(0);

        // produce stage it+2 into buffer pidx (hidden under ks0 MMA drain)
        if (it + 2 < NIT) {
            if (it >= 1) NBAR_SYNC(1 + pidx);     // all warps released buffer pidx
            load_stage_to(pbuf, gA, gB);
            CPASYNC_ARRIVE(mfull + pidx * 8);
            gA += 64; gB += 64;
        }

        ldA(1, baseA, 32);  ldB(1, baseB, 32);    // ks1 frags
        mma_batch(1);
        ldA(0, baseA, 64);  ldB(0, baseB, 64);    // ks2 frags
        mma_batch(0);
        ldA(1, baseA, 96);  ldB(1, baseB, 96);    // ks3 frags
        mma_batch(1);                              // issued BEFORE the full-wait

        // stage reads done (last LDSMs issued above); release + advance + prefetch
        NBAR_ARRIVE(1 + cidx);
        cidx++; cbuf += STAGE; if (cidx == S) { cidx = 0; cbuf = tiles; cph ^= 1; }
        if (it + 1 < NIT) {
            MBAR_WAIT(mfull + cidx * 8, cph);      // hidden under ks3 MMA drain
            baseA = cbuf + aP0;
            baseB = cbuf + A_BYTES + bP0;
            ldA(0, baseA, 0);
            ldB(0, baseB, 0);
        }
        pidx++; pbuf += STAGE; if (pidx == S) { pidx = 0; pbuf = tiles; }
    }

    // ---- epilogue (register-only inputs; no sync needed) ----
    const int qg = lid >> 2;            // row within 8
    const int qc = (lid & 3) * 2;       // col pair
#pragma unroll
    for (int mi = 0; mi < 4; mi++) {
#pragma unroll
        for (int ni = 0; ni < 4; ni++) {
            int r = m0 + wm * 64 + mi * 16 + qg;
            int n = n0 + wn * 32 + ni * 8 + qc;
            float s0 = __ldg(scales + n);
            float s1 = __ldg(scales + n + 1);
            float v00 = c[mi][ni][0] * s0, v01 = c[mi][ni][1] * s1;
            float v10 = c[mi][ni][2] * s0, v11 = c[mi][ni][3] * s1;
            if constexpr (GELU_OUT) {
                __half2 h0 = __floats2half2_rn(gelu_tanh(v00), gelu_tanh(v01));
                __half2 h1 = __floats2half2_rn(gelu_tanh(v10), gelu_tanh(v11));
                *reinterpret_cast<__half2*>((__half*)C + (size_t)r * Ncols + n) = h0;
                *reinterpret_cast<__half2*>((__half*)C + (size_t)(r + 8) * Ncols + n) = h1;
            } else {
                *reinterpret_cast<float2*>((float*)C + (size_t)r * Ncols + n) = make_float2(v00, v01);
                *reinterpret_cast<float2*>((float*)C + (size_t)(r + 8) * Ncols + n) = make_float2(v10, v11);
            }
        }
    }
}

// ---------------- launch ----------------
extern "C" void kernel_launch(void* const* d_in, const int* in_sizes, int n_in,
                              void* d_out, int out_size)
{
    const float* x   = (const float*)d_in[0];
    const int*   w1p = (const int*)  d_in[1];
    const float* s1  = (const float*)d_in[2];
    const int*   w2p = (const int*)  d_in[3];
    const float* s2  = (const float*)d_in[4];
    float*       out = (float*)d_out;

    __half *px, *pw1, *pw2, *ph;
    cudaGetSymbolAddress((void**)&px,  g_x16);
    cudaGetSymbolAddress((void**)&pw1, g_w1);
    cudaGetSymbolAddress((void**)&pw2, g_w2);
    cudaGetSymbolAddress((void**)&ph,  g_h);

    const int smem_bytes = 3 * (128 * 128 * 2) + 1024;  // 99328 (incl. align pad)
    cudaFuncSetAttribute(
        (const void*)qmlp_gemm<true,  __half, D_MODEL, D_MODEL>,
        cudaFuncAttributeMaxDynamicSharedMemorySize, smem_bytes);
    cudaFuncSetAttribute(
        (const void*)qmlp_gemm<false, float, HIDDEN, HIDDEN>,
        cudaFuncAttributeMaxDynamicSharedMemorySize, smem_bytes);

    // 1. fused prep: x -> fp16 and int4 weights -> fp16 (one launch, 32B/thread)
    {
        int n4x = N_TOKENS * D_MODEL / 4;
        int n41 = HIDDEN * (D_MODEL / 2) / 4;
        int n42 = D_MODEL * (HIDDEN / 2) / 4;
        int threads_total = (n4x + n41 + n42) / 2;
        k_prep<<<(threads_total + 255) / 256, 256>>>(
            (const float4*)x, (uint2*)px,
            (const int4*)w1p, (uint4*)pw1,
            (const int4*)w2p, (uint4*)pw2,
            n4x, n41, n42);
    }
    // 2. h = gelu((x @ W1int^T) * s1)   [4096, 16384] fp16
    {
        dim3 grid((N_TOKENS / 128) * (HIDDEN / 128));
        qmlp_gemm<true, __half, D_MODEL, D_MODEL><<<grid, 256, smem_bytes>>>(
            px, pw1, s1, ph, N_TOKENS, HIDDEN);
    }
    // 3. out = (h @ W2int^T) * s2       [4096, 4096] fp32
    {
        dim3 grid((N_TOKENS / 128) * (D_MODEL / 128));
        qmlp_gemm<false, float, HIDDEN, HIDDEN><<<grid, 256, smem_bytes>>>(
            ph, pw2, s2, out, N_TOKENS, D_MODEL);
    }
}

// round 16
// speedup vs baseline: 1.1589x; 1.1589x over previous
#include <cuda_runtime.h>
#include <cuda_fp16.h>
#include <cstdint>

#define N_TOKENS 4096
#define D_MODEL  4096
#define HIDDEN   16384

// ---------------- device scratch (no runtime allocation allowed) ----------------
__device__ __align__(1024) __half g_x16[(size_t)N_TOKENS * D_MODEL];   //  32 MB
__device__ __align__(1024) __half g_w1 [(size_t)HIDDEN   * D_MODEL];   // 128 MB
__device__ __align__(1024) __half g_w2 [(size_t)D_MODEL  * HIDDEN];    // 128 MB
__device__ __align__(1024) __half g_h  [(size_t)N_TOKENS * HIDDEN];    // 128 MB

// ---------------- helpers ----------------
static __device__ __forceinline__ uint32_t smem_u32(const void* p) {
    uint32_t a;
    asm("{ .reg .u64 t; cvta.to.shared.u64 t, %1; cvt.u32.u64 %0, t; }" : "=r"(a) : "l"(p));
    return a;
}

static __device__ __forceinline__ void cp_async16(uint32_t dst, const void* src) {
    asm volatile("cp.async.cg.shared.global [%0], [%1], 16;" :: "r"(dst), "l"(src) : "memory");
}

#define MBARRIER_INIT(addr, cnt) \
    asm volatile("mbarrier.init.shared.b64 [%0], %1;" :: "r"(addr), "r"(cnt) : "memory")

// arrive on mbarrier when all of this thread's prior cp.asyncs have completed
#define CPASYNC_ARRIVE(addr) \
    asm volatile("cp.async.mbarrier.arrive.noinc.shared.b64 [%0];" :: "r"(addr) : "memory")

#define MBARRIER_ARRIVE(addr) \
    asm volatile("mbarrier.arrive.shared.b64 _, [%0];" :: "r"(addr) : "memory")

// acquire wait: post-wait generic-proxy reads (LDSM) need the acquire
#define MBAR_WAIT(addr, ph) do {                                                     \
    uint32_t _m = (addr); uint32_t _p = (uint32_t)(ph); uint32_t _done;              \
    asm volatile("{\n\t.reg .pred p;\n\t"                                            \
        "mbarrier.try_wait.parity.acquire.cta.shared::cta.b64 p, [%1], %2;\n\t"      \
        "selp.b32 %0, 1, 0, p;\n\t}"                                                 \
        : "=r"(_done) : "r"(_m), "r"(_p) : "memory");                                \
    if (!_done) {                                                                    \
        asm volatile("{\n\t.reg .pred P1;\n\t"                                       \
            "WL_%=:\n\t"                                                             \
            "mbarrier.try_wait.parity.acquire.cta.shared::cta.b64 P1, [%0], %1, 0x989680;\n\t" \
            "@P1 bra.uni WD_%=;\n\t"                                                 \
            "bra.uni WL_%=;\n\t"                                                     \
            "WD_%=:\n\t}"                                                            \
            :: "r"(_m), "r"(_p) : "memory");                                         \
    }                                                                                \
} while (0)

// relaxed wait: producer only — post-wait accesses are async-proxy cp.asyncs
#define MBAR_WAIT_RELAXED(addr, ph) do {                                             \
    uint32_t _m = (addr); uint32_t _p = (uint32_t)(ph); uint32_t _done;              \
    asm volatile("{\n\t.reg .pred p;\n\t"                                            \
        "mbarrier.try_wait.parity.relaxed.cta.shared::cta.b64 p, [%1], %2;\n\t"      \
        "selp.b32 %0, 1, 0, p;\n\t}"                                                 \
        : "=r"(_done) : "r"(_m), "r"(_p) : "memory");                                \
    if (!_done) {                                                                    \
        asm volatile("{\n\t.reg .pred P1;\n\t"                                       \
            "WL_%=:\n\t"                                                             \
            "mbarrier.try_wait.parity.relaxed.cta.shared::cta.b64 P1, [%0], %1, 0x989680;\n\t" \
            "@P1 bra.uni WD_%=;\n\t"                                                 \
            "bra.uni WL_%=;\n\t"                                                     \
            "WD_%=:\n\t}"                                                            \
            :: "r"(_m), "r"(_p) : "memory");                                         \
    }                                                                                \
} while (0)

static __device__ __forceinline__ void ldmatrix_x4(uint32_t& r0, uint32_t& r1,
                                                   uint32_t& r2, uint32_t& r3, uint32_t addr) {
    asm volatile("ldmatrix.sync.aligned.m8n8.x4.shared.b16 {%0,%1,%2,%3}, [%4];"
                 : "=r"(r0), "=r"(r1), "=r"(r2), "=r"(r3) : "r"(addr));
}

static __device__ __forceinline__ void mma_16816(float* c, const uint32_t* a,
                                                 const uint32_t* b) {
    asm volatile(
        "mma.sync.aligned.m16n8k16.row.col.f32.f16.f16.f32 "
        "{%0,%1,%2,%3}, {%4,%5,%6,%7}, {%8,%9}, {%0,%1,%2,%3};"
        : "+f"(c[0]), "+f"(c[1]), "+f"(c[2]), "+f"(c[3])
        : "r"(a[0]), "r"(a[1]), "r"(a[2]), "r"(a[3]), "r"(b[0]), "r"(b[1]));
}

static __device__ __forceinline__ float gelu_tanh(float v) {
    // JAX default: gelu(x) = 0.5 x (1 + tanh(sqrt(2/pi) (x + 0.044715 x^3)))
    float u = 0.7978845608028654f * (v + 0.044715f * v * v * v);
    float e = __expf(2.0f * u);
    float t = 1.0f - 2.0f / (e + 1.0f);     // tanh(u), correct limits at +-inf
    return 0.5f * v * (1.0f + t);
}

// ---------------- fused prep kernel: x->fp16 + both int4 dequants, 32B/thread ----
static __device__ __forceinline__ uint32_t unpack_pair(int p) {
    p &= 255;
    __half2 h = __halves2half2(__int2half_rn((p >> 4) - 8), __int2half_rn((p & 15) - 8));
    return reinterpret_cast<uint32_t&>(h);
}

__global__ void k_prep(const float4* __restrict__ x, uint2* __restrict__ x16,
                       const int4* __restrict__ p1, uint4* __restrict__ w1,
                       const int4* __restrict__ p2, uint4* __restrict__ w2,
                       int n4x, int n41, int n42) {
    int i = (blockIdx.x * blockDim.x + threadIdx.x) * 2;   // 2 x 16B chunks per thread
    if (i < n4x) {
#pragma unroll
        for (int j = 0; j < 2; j++) {
            float4 v = x[i + j];
            __half2 a = __floats2half2_rn(v.x, v.y);
            __half2 b = __floats2half2_rn(v.z, v.w);
            uint2 o;
            o.x = reinterpret_cast<uint32_t&>(a);
            o.y = reinterpret_cast<uint32_t&>(b);
            x16[i + j] = o;
        }
        return;
    }
    i -= n4x;
    if (i < n41) {
#pragma unroll
        for (int j = 0; j < 2; j++) {
            int4 v = p1[i + j];
            uint4 o;
            o.x = unpack_pair(v.x); o.y = unpack_pair(v.y);
            o.z = unpack_pair(v.z); o.w = unpack_pair(v.w);
            w1[i + j] = o;
        }
        return;
    }
    i -= n41;
    if (i < n42) {
#pragma unroll
        for (int j = 0; j < 2; j++) {
            int4 v = p2[i + j];
            uint4 o;
            o.x = unpack_pair(v.x); o.y = unpack_pair(v.y);
            o.z = unpack_pair(v.z); o.w = unpack_pair(v.w);
            w2[i + j] = o;
        }
    }
}

// ---------------- HMMA GEMM: C[M,N] = A[M,0:KSPAN] * B[N,0:KSPAN]^T ----------------
// A, B fp16 K-major with COMPILE-TIME row stride KLD and span KSPAN.
// CTA 128x128x64, 256 thr, 8 warps (2x4), warp tile 64x32, 3-stage mbarrier
// producer/consumer pipeline (full: cp.async-armed mbarrier; empty: mbarrier with
// one arrive per warp — per-warp slip preserved, NO blocking named barriers).
// Fully double-buffered A+B fragments; waits issued after MMA batches so the
// tensor-pipe backlog covers them. (R14 kernel, verbatim.)
template <bool GELU_OUT, typename OutT, int KLD, int KSPAN>
__global__ void __launch_bounds__(256, 2)
qmlp_gemm(const __half* __restrict__ A, const __half* __restrict__ B,
          const float* __restrict__ scales, OutT* __restrict__ C,
          int M, int Ncols)
{
    constexpr int S        = 3;
    constexpr int A_BYTES  = 128 * 128;         // 128 rows x 64 halves
    constexpr int B_BYTES  = 128 * 128;
    constexpr int STAGE    = A_BYTES + B_BYTES; // 32 KB
    constexpr int NIT      = KSPAN >> 6;        // K-tiles of 64

    extern __shared__ unsigned char dynsmem[];
    __shared__ __align__(8) uint64_t s_mbar[2 * S];   // full[0..2], empty[0..2]

    const uint32_t sbase0 = smem_u32(dynsmem);
    const uint32_t tiles  = (sbase0 + 1023u) & ~1023u;   // 1KB-align (XOR trick needs 128B)
    const uint32_t mfull  = smem_u32(&s_mbar[0]);        // + b*8
    const uint32_t mempty = smem_u32(&s_mbar[S]);        // + b*8

    const int tid = threadIdx.x;
    const int wid = tid >> 5;
    const int lid = tid & 31;
    const int wm  = wid & 1;                    // 2 warps along M
    const int wn  = wid >> 1;                   // 4 warps along N

    // block -> (m-tile, n-tile), grouped along M for L2 reuse of B
    const int mt_tiles = M >> 7;
    const int nt_tiles = Ncols >> 7;
    const int GROUPM = 8;
    const int per_group = GROUPM * nt_tiles;
    int g  = blockIdx.x / per_group;
    int rr = blockIdx.x - g * per_group;
    int gm = mt_tiles - g * GROUPM; if (gm > GROUPM) gm = GROUPM;
    const int m0 = (g * GROUPM + (rr % gm)) << 7;
    const int n0 = (rr / gm) << 7;

    if (tid == 0) {
#pragma unroll
        for (int b = 0; b < S; b++) {
            MBARRIER_INIT(mfull + b * 8, 256);  // flips when all threads' cp.asyncs land
            MBARRIER_INIT(mempty + b * 8, 8);   // one arrive per warp after last LDSM
        }
    }
    __syncthreads();                            // barriers visible; only CTA-wide sync

    // ---- precomputed per-thread offsets (SW128 decomposition) ----
    const int lrow = tid >> 3;                  // 0..31
    const int lseg = tid & 7;                   // 16B segment in 128B row
    const uint32_t dst0 = (uint32_t)(lrow * 128 + ((lseg * 16) ^ ((lrow & 7) << 4)));

    const int a_row = wm * 64 + (lid & 15);
    const uint32_t a_cb = (uint32_t)((lid >> 4) << 4);            // 0 or 16 bytes
    const int b_row = wn * 32 + (lid & 7) + ((lid & 16) ? 8 : 0);
    const uint32_t b_cb = (uint32_t)((lid & 8) ? 16 : 0);
    const uint32_t aP0 = (uint32_t)(a_row * 128) + (a_cb ^ (uint32_t)((a_row & 7) << 4));
    const uint32_t bP0 = (uint32_t)(b_row * 128) + (b_cb ^ (uint32_t)((b_row & 7) << 4));

    // global source pointers, advanced 64 halves (128B) per stage
    const __half* gA = A + (size_t)(m0 + lrow) * KLD + lseg * 8;
    const __half* gB = B + (size_t)(n0 + lrow) * KLD + lseg * 8;
    constexpr size_t rowblk = (size_t)32 * KLD;   // 32-row chunk stride (elements)

    auto load_stage_to = [&](uint32_t st, const __half* a_, const __half* b_) {
#pragma unroll
        for (int i = 0; i < 4; i++)
            cp_async16(st + dst0 + i * 4096, a_ + i * rowblk);
#pragma unroll
        for (int i = 0; i < 4; i++)
            cp_async16(st + A_BYTES + dst0 + i * 4096, b_ + i * rowblk);
    };

    float c[4][4][4];
#pragma unroll
    for (int i = 0; i < 4; i++)
#pragma unroll
        for (int j = 0; j < 4; j++)
#pragma unroll
            for (int k = 0; k < 4; k++) c[i][j][k] = 0.0f;

    // fully double-buffered fragments
    uint32_t afr[2][4][4];
    uint32_t bfr[2][4][2];

    auto ldA = [&](int buf, uint32_t baseA, uint32_t kx) {
        const uint32_t bk = baseA ^ kx;
#pragma unroll
        for (int mi = 0; mi < 4; mi++)
            ldmatrix_x4(afr[buf][mi][0], afr[buf][mi][1], afr[buf][mi][2], afr[buf][mi][3],
                        bk + mi * 2048);
    };
    auto ldB = [&](int buf, uint32_t baseB, uint32_t kx) {
        const uint32_t bk = baseB ^ kx;
#pragma unroll
        for (int p = 0; p < 2; p++) {
            uint32_t r0, r1, r2, r3;
            ldmatrix_x4(r0, r1, r2, r3, bk + p * 2048);
            bfr[buf][2 * p][0] = r0; bfr[buf][2 * p][1] = r1;
            bfr[buf][2 * p + 1][0] = r2; bfr[buf][2 * p + 1][1] = r3;
        }
    };
    auto mma_batch = [&](int fb) {
#pragma unroll
        for (int mi = 0; mi < 4; mi++)
#pragma unroll
            for (int ni = 0; ni < 4; ni++)
                mma_16816(c[mi][ni], afr[fb][mi], bfr[fb][ni]);
    };

    // prologue: stages 0 and 1, each armed with a DMA-completion arrive
    load_stage_to(tiles, gA, gB);
    CPASYNC_ARRIVE(mfull + 0 * 8);
    load_stage_to(tiles + STAGE, gA + 64, gB + 64);
    CPASYNC_ARRIVE(mfull + 1 * 8);
    gA += 128; gB += 128;

    // consumer cursor: buffer cidx, parity cph
    int cidx = 0, cph = 0;
    uint32_t cbuf = tiles;
    // producer cursor: buffer pidx = (it+2)%3, empty parity pph
    int pidx = 2, pph = 1;
    uint32_t pbuf = tiles + 2 * STAGE;

    // consumer prologue: wait stage 0, load ks=0 frags into buffer 0
    MBAR_WAIT(mfull + 0, 0);
    uint32_t baseA = cbuf + aP0;
    uint32_t baseB = cbuf + A_BYTES + bP0;
    ldA(0, baseA, 0);
    ldB(0, baseB, 0);

#pragma unroll 1
    for (int it = 0; it < NIT; it++) {
        // ks=0 MMAs first — their drain covers the empty-wait below
        mma_batch(0);

        // produce stage it+2 into buffer pidx (hidden under ks0 MMA drain)
        if (it + 2 < NIT) {
            if (it >= 1) MBAR_WAIT_RELAXED(mempty + pidx * 8, pph);
            load_stage_to(pbuf, gA, gB);
            CPASYNC_ARRIVE(mfull + pidx * 8);
            gA += 64; gB += 64;
        }

        ldA(1, baseA, 32);  ldB(1, baseB, 32);    // ks1 frags
        mma_batch(1);
        ldA(0, baseA, 64);  ldB(0, baseB, 64);    // ks2 frags
        mma_batch(0);
        ldA(1, baseA, 96);  ldB(1, baseB, 96);    // ks3 frags
        mma_batch(1);                              // issued BEFORE the full-wait

        // stage reads done (last LDSMs issued above); release + advance + prefetch
        if (lid == 0) MBARRIER_ARRIVE(mempty + cidx * 8);
        cidx++; cbuf += STAGE; if (cidx == S) { cidx = 0; cbuf = tiles; cph ^= 1; }
        if (it + 1 < NIT) {
            MBAR_WAIT(mfull + cidx * 8, cph);      // hidden under ks3 MMA drain
            baseA = cbuf + aP0;
            baseB = cbuf + A_BYTES + bP0;
            ldA(0, baseA, 0);
            ldB(0, baseB, 0);
        }
        pidx++; pbuf += STAGE; if (pidx == S) { pidx = 0; pbuf = tiles; pph ^= 1; }
    }

    // ---- epilogue (register-only inputs; no sync needed) ----
    const int qg = lid >> 2;            // row within 8
    const int qc = (lid & 3) * 2;       // col pair
#pragma unroll
    for (int mi = 0; mi < 4; mi++) {
#pragma unroll
        for (int ni = 0; ni < 4; ni++) {
            int r = m0 + wm * 64 + mi * 16 + qg;
            int n = n0 + wn * 32 + ni * 8 + qc;
            float s0 = __ldg(scales + n);
            float s1 = __ldg(scales + n + 1);
            float v00 = c[mi][ni][0] * s0, v01 = c[mi][ni][1] * s1;
            float v10 = c[mi][ni][2] * s0, v11 = c[mi][ni][3] * s1;
            if constexpr (GELU_OUT) {
                __half2 h0 = __floats2half2_rn(gelu_tanh(v00), gelu_tanh(v01));
                __half2 h1 = __floats2half2_rn(gelu_tanh(v10), gelu_tanh(v11));
                *reinterpret_cast<__half2*>((__half*)C + (size_t)r * Ncols + n) = h0;
                *reinterpret_cast<__half2*>((__half*)C + (size_t)(r + 8) * Ncols + n) = h1;
            } else {
                *reinterpret_cast<float2*>((float*)C + (size_t)r * Ncols + n) = make_float2(v00, v01);
                *reinterpret_cast<float2*>((float*)C + (size_t)(r + 8) * Ncols + n) = make_float2(v10, v11);
            }
        }
    }
}

// ---------------- launch ----------------
extern "C" void kernel_launch(void* const* d_in, const int* in_sizes, int n_in,
                              void* d_out, int out_size)
{
    const float* x   = (const float*)d_in[0];
    const int*   w1p = (const int*)  d_in[1];
    const float* s1  = (const float*)d_in[2];
    const int*   w2p = (const int*)  d_in[3];
    const float* s2  = (const float*)d_in[4];
    float*       out = (float*)d_out;

    __half *px, *pw1, *pw2, *ph;
    cudaGetSymbolAddress((void**)&px,  g_x16);
    cudaGetSymbolAddress((void**)&pw1, g_w1);
    cudaGetSymbolAddress((void**)&pw2, g_w2);
    cudaGetSymbolAddress((void**)&ph,  g_h);

    const int smem_bytes = 3 * (128 * 128 * 2) + 1024;  // 99328 (incl. align pad)
    cudaFuncSetAttribute(
        (const void*)qmlp_gemm<true,  __half, D_MODEL, D_MODEL>,
        cudaFuncAttributeMaxDynamicSharedMemorySize, smem_bytes);
    cudaFuncSetAttribute(
        (const void*)qmlp_gemm<false, float, HIDDEN, HIDDEN>,
        cudaFuncAttributeMaxDynamicSharedMemorySize, smem_bytes);

    // 1. fused prep: x -> fp16 and int4 weights -> fp16 (one launch, 32B/thread)
    {
        int n4x = N_TOKENS * D_MODEL / 4;
        int n41 = HIDDEN * (D_MODEL / 2) / 4;
        int n42 = D_MODEL * (HIDDEN / 2) / 4;
        int threads_total = (n4x + n41 + n42) / 2;
        k_prep<<<(threads_total + 255) / 256, 256>>>(
            (const float4*)x, (uint2*)px,
            (const int4*)w1p, (uint4*)pw1,
            (const int4*)w2p, (uint4*)pw2,
            n4x, n41, n42);
    }
    // 2. h = gelu((x @ W1int^T) * s1)   [4096, 16384] fp16
    {
        dim3 grid((N_TOKENS / 128) * (HIDDEN / 128));
        qmlp_gemm<true, __half, D_MODEL, D_MODEL><<<grid, 256, smem_bytes>>>(
            px, pw1, s1, ph, N_TOKENS, HIDDEN);
    }
    // 3. out = (h @ W2int^T) * s2       [4096, 4096] fp32
    {
        dim3 grid((N_TOKENS / 128) * (D_MODEL / 128));
        qmlp_gemm<false, float, HIDDEN, HIDDEN><<<grid, 256, smem_bytes>>>(
            ph, pw2, s2, out, N_TOKENS, D_MODEL);
    }
}